// round 14
// baseline (speedup 1.0000x reference)
#include <cuda_runtime.h>
#include <cuda_bf16.h>
#include <cstdint>

// Fixed shapes
#define BB 4
#define CC 256
#define PP 1024
#define NK 8192
#define AA 64
#define PL (PP * NK)
#define PVSPLIT 4

// -------- device scratch --------
__device__ unsigned g_q[BB * PP * AA / 2];            // [b][p][a/2] bf16x2
__device__ unsigned g_k[BB * NK * AA / 2];            // [b][k][a/2]
__device__ unsigned g_vt[BB * CC * NK / 2];           // [b][c][k/2]  (V^T)
__device__ unsigned g_P[(size_t)BB * PL / 2];         // [b][p][k/2]
__device__ float g_peq[PP * AA];
__device__ float g_pek[PP * AA];
__device__ float g_part[PVSPLIT * BB * PP * CC];      // fp32 partials

// -------- helpers --------
__device__ __forceinline__ uint32_t f2tf(float f) {
    uint32_t r;
    asm("cvt.rna.tf32.f32 %0, %1;" : "=r"(r) : "f"(f));
    return r;
}
__device__ __forceinline__ unsigned pack_bf16(float lo, float hi) {
    unsigned r;
    asm("cvt.rn.bf16x2.f32 %0, %1, %2;" : "=r"(r) : "f"(hi), "f"(lo));
    return r;
}
__device__ __forceinline__ void mma8(float* c, const uint32_t* a, const uint32_t* b) {
    asm volatile("mma.sync.aligned.m16n8k8.row.col.f32.tf32.tf32.f32 "
                 "{%0,%1,%2,%3}, {%4,%5,%6,%7}, {%8,%9}, {%0,%1,%2,%3};"
                 : "+f"(c[0]), "+f"(c[1]), "+f"(c[2]), "+f"(c[3])
                 : "r"(a[0]), "r"(a[1]), "r"(a[2]), "r"(a[3]), "r"(b[0]), "r"(b[1]));
}
__device__ __forceinline__ void mma16(float* c, const unsigned* a, const unsigned* b) {
    asm volatile("mma.sync.aligned.m16n8k16.row.col.f32.bf16.bf16.f32 "
                 "{%0,%1,%2,%3}, {%4,%5,%6,%7}, {%8,%9}, {%0,%1,%2,%3};"
                 : "+f"(c[0]), "+f"(c[1]), "+f"(c[2]), "+f"(c[3])
                 : "r"(a[0]), "r"(a[1]), "r"(a[2]), "r"(a[3]), "r"(b[0]), "r"(b[1]));
}
__device__ __forceinline__ void ldm_x4(unsigned* r, uint32_t addr) {
    asm volatile("ldmatrix.sync.aligned.m8n8.x4.shared.b16 {%0,%1,%2,%3}, [%4];"
                 : "=r"(r[0]), "=r"(r[1]), "=r"(r[2]), "=r"(r[3]) : "r"(addr));
}
__device__ __forceinline__ uint4 cvt4(float4 v) {
    uint4 r;
    r.x = f2tf(v.x); r.y = f2tf(v.y); r.z = f2tf(v.z); r.w = f2tf(v.w);
    return r;
}
__device__ __forceinline__ void cp_async16(uint32_t dst, const void* src) {
    asm volatile("cp.async.cg.shared.global [%0], [%1], 16;" :: "r"(dst), "l"(src));
}
#define CP_COMMIT() asm volatile("cp.async.commit_group;")
template<int N> __device__ __forceinline__ void cp_wait() {
    asm volatile("cp.async.wait_group %0;" :: "n"(N));
}
__device__ __forceinline__ uint32_t smem_u32(const void* p) {
    return (uint32_t)__cvta_generic_to_shared(p);
}

// Lane-offset builders for ldmatrix (row stride 36 uints).
__device__ __forceinline__ int laneA_off(int L) {
    return ((((L >> 3) & 1) * 8 + (L & 7)) * 36 + (L >> 4) * 4) * 4;
}
__device__ __forceinline__ int laneB_off(int L) {
    return (((L >> 4) * 8 + (L & 7)) * 36 + ((L >> 3) & 1) * 4) * 4;
}

// ============================================================================
// Kernel 1: positional-encoding projections pe_q / pe_k  [1024, 64] (fp32)
// ============================================================================
__global__ void pe_proj_kernel(const float* __restrict__ Wpx, const float* __restrict__ bpx,
                               const float* __restrict__ Wpy, const float* __restrict__ bpy) {
    int p = blockIdx.x;
    int y = p >> 5, x = p & 31;
    const float* W = blockIdx.y ? Wpy : Wpx;
    const float* bb = blockIdx.y ? bpy : bpx;
    float* outp = blockIdx.y ? g_pek : g_peq;

    __shared__ float pe[CC];
    int c = threadIdx.x;
    {
        int pos = (c < 128) ? y : x;
        int idx = (c < 128) ? c : (c - 128);
        int j = idx >> 1;
        float ang = (float)pos * expf(-logf(10000.0f) * (float)j / 64.0f);
        pe[c] = (idx & 1) ? cosf(ang) : sinf(ang);
    }
    __syncthreads();
    if (c < AA) {
        float s = 0.0f;
        #pragma unroll 8
        for (int i = 0; i < CC; i++) s += pe[i] * W[c * CC + i];
        outp[p * AA + c] = s + bb[c];
    }
}

// ============================================================================
// proj body: tf32 GEMM -> bf16 outputs, register-pipelined (streaming A loads)
// ============================================================================
__device__ __forceinline__ void proj_body(uint32_t* sm_, int m0, int n0, int z,
                                          const float* __restrict__ A,
                                          const float* __restrict__ W,
                                          const float* __restrict__ bias,
                                          int N, int mode) {
    uint32_t (*As)[136] = (uint32_t(*)[136])sm_;
    uint32_t (*Ws)[36]  = (uint32_t(*)[36])(sm_ + 32 * 136);

    A += (size_t)z * CC * PP;

    int tid = threadIdx.x;
    int wid = tid >> 5;
    int g = (tid >> 2) & 7, tg = tid & 3;
    int mbase = (wid >> 1) * 32;
    int nbase = (wid & 1) * 32;

    float acc[2][4][4];
    #pragma unroll
    for (int i = 0; i < 2; i++)
        #pragma unroll
        for (int j = 0; j < 4; j++)
            #pragma unroll
            for (int r = 0; r < 4; r++) acc[i][j][r] = 0.0f;

    float4 ar[4], wr[2];
    auto ldA = [&](int c0) {
        #pragma unroll
        for (int i = 0; i < 4; i++) {
            int idx = i * 256 + tid;
            int row = idx >> 5, c4 = idx & 31;
            ar[i] = __ldcs((const float4*)&A[(size_t)(c0 + row) * PP + m0 + c4 * 4]);
        }
    };
    auto ldW = [&](int c0) {
        #pragma unroll
        for (int i = 0; i < 2; i++) {
            int idx = i * 256 + tid;
            int row = idx >> 3, c4 = idx & 7;
            wr[i] = *(const float4*)&W[(size_t)(n0 + row) * CC + c0 + c4 * 4];
        }
    };

    ldA(0); ldW(0);

    for (int c0 = 0; c0 < CC; c0 += 32) {
        #pragma unroll
        for (int i = 0; i < 4; i++) {
            int idx = i * 256 + tid;
            int row = idx >> 5, c4 = idx & 31;
            *(uint4*)&As[row][c4 * 4] = cvt4(ar[i]);
        }
        #pragma unroll
        for (int i = 0; i < 2; i++) {
            int idx = i * 256 + tid;
            int row = idx >> 3, c4 = idx & 7;
            *(uint4*)&Ws[row][c4 * 4] = cvt4(wr[i]);
        }
        __syncthreads();

        if (c0 + 32 < CC) { ldA(c0 + 32); ldW(c0 + 32); }

        #pragma unroll
        for (int ks = 0; ks < 4; ks++) {
            int k0 = ks * 8;
            uint32_t af[2][4], bf[4][2];
            #pragma unroll
            for (int mt = 0; mt < 2; mt++) {
                int mr = mbase + mt * 16;
                af[mt][0] = As[k0 + tg][mr + g];
                af[mt][1] = As[k0 + tg][mr + g + 8];
                af[mt][2] = As[k0 + tg + 4][mr + g];
                af[mt][3] = As[k0 + tg + 4][mr + g + 8];
            }
            #pragma unroll
            for (int nt = 0; nt < 4; nt++) {
                int nr = nbase + nt * 8;
                bf[nt][0] = Ws[nr + g][k0 + tg];
                bf[nt][1] = Ws[nr + g][k0 + tg + 4];
            }
            #pragma unroll
            for (int mt = 0; mt < 2; mt++)
                #pragma unroll
                for (int nt = 0; nt < 4; nt++)
                    mma8(acc[mt][nt], af[mt], bf[nt]);
        }
        __syncthreads();
    }

    if (mode < 2) {
        const float* extra = (mode == 0) ? g_peq : g_pek;
        unsigned* C = (mode == 0 ? g_q : g_k) + (size_t)z * PP * (N / 2);
        #pragma unroll
        for (int mt = 0; mt < 2; mt++) {
            int r0 = m0 + mbase + mt * 16 + g;
            #pragma unroll
            for (int nt = 0; nt < 4; nt++) {
                int col = n0 + nbase + nt * 8 + 2 * tg;
                float b0 = bias[col], b1 = bias[col + 1];
                float e00 = extra[r0 * AA + col],       e01 = extra[r0 * AA + col + 1];
                float e10 = extra[(r0 + 8) * AA + col], e11 = extra[(r0 + 8) * AA + col + 1];
                C[r0 * (N / 2) + col / 2] =
                    pack_bf16(acc[mt][nt][0] + b0 + e00, acc[mt][nt][1] + b1 + e01);
                C[(r0 + 8) * (N / 2) + col / 2] =
                    pack_bf16(acc[mt][nt][2] + b0 + e10, acc[mt][nt][3] + b1 + e11);
            }
        }
    } else {
        __nv_bfloat16* Cs = (__nv_bfloat16*)sm_;   // 64 x 132 bf16 rows (66 uints)
        #pragma unroll
        for (int mt = 0; mt < 2; mt++) {
            int r0 = mbase + mt * 16 + g;
            #pragma unroll
            for (int nt = 0; nt < 4; nt++) {
                int col = nbase + nt * 8 + 2 * tg;
                float b0 = bias[n0 + col], b1 = bias[n0 + col + 1];
                Cs[(col)     * 132 + r0]     = __float2bfloat16(acc[mt][nt][0] + b0);
                Cs[(col + 1) * 132 + r0]     = __float2bfloat16(acc[mt][nt][1] + b1);
                Cs[(col)     * 132 + r0 + 8] = __float2bfloat16(acc[mt][nt][2] + b0);
                Cs[(col + 1) * 132 + r0 + 8] = __float2bfloat16(acc[mt][nt][3] + b1);
            }
        }
        __syncthreads();
        int b = z >> 3, page = z & 7;
        const unsigned* Csu = (const unsigned*)Cs;
        int tid2 = threadIdx.x;
        #pragma unroll
        for (int j = 0; j < 16; j++) {
            int f = j * 256 + tid2;
            int n = f >> 6, u = f & 63;
            g_vt[(size_t)(b * CC + n0 + n) * (NK / 2) + page * 512 + m0 / 2 + u] =
                Csu[n * 66 + u];
        }
    }
}

// ============================================================================
// qk body: QK^T (bf16, ldmatrix) + register-local batch softmax -> P (bf16),
// smem-staged coalesced P writes (plain stores: keep P resident in L2 for pv).
// ============================================================================
#define QK_TILE (4 * 64 * 36)
#define QK_SMEM_BYTES (2 * QK_TILE * 4)   // 73728 B

__device__ __forceinline__ void qk_body(uint32_t* sm_, int qtile, int ktile) {
    const uint32_t sb = smem_u32(sm_);

    const int tid = threadIdx.x;
    const int wid = tid >> 5;
    const int L = tid & 31;
    const int g = (tid >> 2) & 7, tg = tid & 3;
    const int qbase = qtile * 64, kbase = ktile * 64;

    #pragma unroll
    for (int j = 0; j < 8; j++) {
        int f = j * 256 + tid;
        int row = f >> 3, a4 = f & 7;
        int b = row >> 6, r = row & 63;
        cp_async16(sb + (row * 36 + a4 * 4) * 4,
                   &g_q[((b << 10) + qbase + r) * 32 + a4 * 4]);
        cp_async16(sb + (QK_TILE + row * 36 + a4 * 4) * 4,
                   &g_k[((b << 13) + kbase + r) * 32 + a4 * 4]);
    }
    CP_COMMIT();
    cp_wait<0>();
    __syncthreads();

    const int wm = wid >> 2, wn = wid & 3;
    const int qrow0 = wm * 32, kcol0 = wn * 16;

    const int aoff = laneA_off(L);
    const int boff = laneB_off(L);
    const uint32_t qa_base = sb + qrow0 * 36 * 4 + aoff;
    const uint32_t kb_base = sb + QK_TILE * 4 + kcol0 * 36 * 4 + boff;

    float acc[4][2][2][4];
    #pragma unroll
    for (int b = 0; b < 4; b++)
        #pragma unroll
        for (int i = 0; i < 2; i++)
            #pragma unroll
            for (int j = 0; j < 2; j++)
                #pragma unroll
                for (int r = 0; r < 4; r++) acc[b][i][j][r] = 0.0f;

    #pragma unroll
    for (int ks = 0; ks < 4; ks++) {
        int k0b = ks * 32;
        #pragma unroll
        for (int b = 0; b < 4; b++) {
            unsigned af[2][4], bf[4];
            ldm_x4(af[0], qa_base + b * 9216 + k0b);
            ldm_x4(af[1], qa_base + b * 9216 + 16 * 36 * 4 + k0b);
            ldm_x4(bf,    kb_base + b * 9216 + k0b);
            #pragma unroll
            for (int mt = 0; mt < 2; mt++)
                #pragma unroll
                for (int nt = 0; nt < 2; nt++)
                    mma16(acc[b][mt][nt], af[mt], bf + nt * 2);
        }
    }

    __syncthreads();
    uint32_t* Ps = sm_;

    #pragma unroll
    for (int mt = 0; mt < 2; mt++) {
        int lo = qrow0 + mt * 16 + g;
        #pragma unroll
        for (int nt = 0; nt < 2; nt++) {
            int cu = kcol0 / 2 + nt * 4 + tg;
            float p[4][4];
            #pragma unroll
            for (int r = 0; r < 4; r++) {
                float s0 = acc[0][mt][nt][r] * 0.125f;
                float s1 = acc[1][mt][nt][r] * 0.125f;
                float s2 = acc[2][mt][nt][r] * 0.125f;
                float s3 = acc[3][mt][nt][r] * 0.125f;
                float m = fmaxf(fmaxf(s0, s1), fmaxf(s2, s3));
                float e0 = __expf(s0 - m), e1 = __expf(s1 - m);
                float e2 = __expf(s2 - m), e3 = __expf(s3 - m);
                float rv = 1.0f / (e0 + e1 + e2 + e3);
                p[r][0] = e0 * rv; p[r][1] = e1 * rv;
                p[r][2] = e2 * rv; p[r][3] = e3 * rv;
            }
            #pragma unroll
            for (int b = 0; b < 4; b++) {
                Ps[b * 2304 + lo * 36 + cu]       = pack_bf16(p[0][b], p[1][b]);
                Ps[b * 2304 + (lo + 8) * 36 + cu] = pack_bf16(p[2][b], p[3][b]);
            }
        }
    }
    __syncthreads();

    #pragma unroll
    for (int j = 0; j < 8; j++) {
        int f = j * 256 + tid;
        int b = f >> 9, r = (f >> 3) & 63, q4 = f & 7;
        uint4 val = *(const uint4*)&Ps[b * 2304 + r * 36 + q4 * 4];
        *(uint4*)&g_P[(size_t)b * (PL / 2) + (size_t)(qbase + r) * (NK / 2)
                      + kbase / 2 + q4 * 4] = val;
    }
}

// ============================================================================
// Kernel 2: merged proj_q + proj_k (288 blocks)
// ============================================================================
__global__ __launch_bounds__(256, 2) void projqk_kernel(
    const float* __restrict__ zx, const float* __restrict__ Wq, const float* __restrict__ bq,
    const float* __restrict__ zy, const float* __restrict__ Wk, const float* __restrict__ bk) {
    extern __shared__ uint32_t sm[];
    int id = blockIdx.x;
    if (id < 32) {
        proj_body(sm, (id & 7) * 128, 0, id >> 3, zx, Wq, bq, 64, 0);
    } else {
        int id2 = id - 32;
        proj_body(sm, (id2 & 7) * 128, 0, id2 >> 3, zy, Wk, bk, 64, 1);
    }
}

// ============================================================================
// Kernel 3: merged proj_v (1024) + qk (2048) = 3072 blocks, 1:2 interleave
// ============================================================================
__global__ __launch_bounds__(256, 2) void projv_qk_kernel(
    const float* __restrict__ zy, const float* __restrict__ Wv, const float* __restrict__ bv) {
    extern __shared__ uint32_t sm[];
    int idx = blockIdx.x;
    if (idx % 3 == 0) {
        int vid = idx / 3;
        proj_body(sm, (vid & 7) * 128, ((vid >> 3) & 3) * 64, vid >> 5, zy, Wv, bv, 256, 2);
    } else {
        int qkid = idx - idx / 3 - 1;
        qk_body(sm, qkid & 15, qkid >> 4);
    }
}

// ============================================================================
// Kernel 4: O = P @ V (bf16, ldmatrix), split-K=4, BK=64, 3-stage pipeline.
// ============================================================================
#define PS_BUF (128 * 36)
#define VS_BUF (128 * 36)
#define STAGE  (PS_BUF + VS_BUF)
#define PV_SMEM_BYTES (3 * STAGE * 4)   // 110592 B

__global__ __launch_bounds__(256, 2) void pv_mma() {
    extern __shared__ uint32_t sm[];
    const uint32_t sb = smem_u32(sm);

    int b = blockIdx.z >> 2;
    int split = blockIdx.z & 3;
    int m0 = blockIdx.x * 128, n0 = blockIdx.y * 128;
    int tid = threadIdx.x;
    int wid = tid >> 5;
    const int L = tid & 31;
    int g = (tid >> 2) & 7, tg = tid & 3;
    int mbase = (wid >> 1) * 32;
    int nbase = (wid & 1) * 64;

    const unsigned* Pu = g_P  + (size_t)b * (PL / 2);
    const unsigned* Vu = g_vt + (size_t)b * CC * (NK / 2);

    const int kstart = split * (NK / PVSPLIT);
    const int NIT = (NK / PVSPLIT) / 64;   // 32

    auto prefetch = [&](int it, int stage) {
        int kbu = (kstart + it * 64) / 2;
        #pragma unroll
        for (int j = 0; j < 4; j++) {
            int f = j * 256 + tid;
            int row = f >> 3, c4 = f & 7;
            uint32_t dst = sb + (stage * STAGE + row * 36 + c4 * 4) * 4;
            cp_async16(dst, Pu + (size_t)(m0 + row) * (NK / 2) + kbu + c4 * 4);
            uint32_t dst2 = sb + (stage * STAGE + PS_BUF + row * 36 + c4 * 4) * 4;
            cp_async16(dst2, Vu + (size_t)(n0 + row) * (NK / 2) + kbu + c4 * 4);
        }
        CP_COMMIT();
    };

    float acc[2][8][4];
    #pragma unroll
    for (int i = 0; i < 2; i++)
        #pragma unroll
        for (int j = 0; j < 8; j++)
            #pragma unroll
            for (int r = 0; r < 4; r++) acc[i][j][r] = 0.0f;

    const int aoff = laneA_off(L);
    const int boff = laneB_off(L);
    const uint32_t pa_base = sb + mbase * 36 * 4 + aoff;
    const uint32_t vb_base = sb + PS_BUF * 4 + nbase * 36 * 4 + boff;

    prefetch(0, 0);
    prefetch(1, 1);

    int stage = 0;
    for (int it = 0; it < NIT; it++) {
        if (it + 1 < NIT) cp_wait<1>(); else cp_wait<0>();
        __syncthreads();
        if (it + 2 < NIT) {
            int ns = stage + 2; if (ns >= 3) ns -= 3;
            prefetch(it + 2, ns);
        }

        uint32_t stg = (uint32_t)(stage * STAGE * 4);
        #pragma unroll
        for (int ks = 0; ks < 4; ks++) {
            int k0b = ks * 32;
            unsigned af[2][4], bf[4][4];
            ldm_x4(af[0], pa_base + stg + k0b);
            ldm_x4(af[1], pa_base + stg + 16 * 36 * 4 + k0b);
            #pragma unroll
            for (int j = 0; j < 4; j++)
                ldm_x4(bf[j], vb_base + stg + j * 16 * 36 * 4 + k0b);
            #pragma unroll
            for (int mt = 0; mt < 2; mt++)
                #pragma unroll
                for (int nt = 0; nt < 8; nt++)
                    mma16(acc[mt][nt], af[mt], bf[nt >> 1] + (nt & 1) * 2);
        }
        if (++stage == 3) stage = 0;
    }

    float* part = g_part + (size_t)split * (BB * PP * CC);
    #pragma unroll
    for (int mt = 0; mt < 2; mt++) {
        int r0 = m0 + mbase + mt * 16 + g;
        #pragma unroll
        for (int nt = 0; nt < 8; nt++) {
            int col = n0 + nbase + nt * 8 + 2 * tg;
            __stcs((float2*)&part[(size_t)((b << 10) + r0) * CC + col],
                   make_float2(acc[mt][nt][0], acc[mt][nt][1]));
            __stcs((float2*)&part[(size_t)((b << 10) + r0 + 8) * CC + col],
                   make_float2(acc[mt][nt][2], acc[mt][nt][3]));
        }
    }
}

// ============================================================================
// Kernel 5: deterministic 4-way split-K reduction into d_out ([b][p][c])
// ============================================================================
__global__ void reduce4(float* __restrict__ out) {
    int i = blockIdx.x * blockDim.x + threadIdx.x;
    const float4* p = (const float4*)g_part;
    const int plane = BB * PP * CC / 4;
    float4 s = __ldcs(p + i);
    #pragma unroll
    for (int sp = 1; sp < PVSPLIT; sp++) {
        float4 t = __ldcs(p + (size_t)sp * plane + i);
        s.x += t.x; s.y += t.y; s.z += t.z; s.w += t.w;
    }
    ((float4*)out)[i] = s;
}

// ============================================================================
extern "C" void kernel_launch(void* const* d_in, const int* in_sizes, int n_in,
                              void* d_out, int out_size) {
    const float* zx  = (const float*)d_in[0];
    const float* zy  = (const float*)d_in[1];
    const float* Wq  = (const float*)d_in[2];
    const float* bq  = (const float*)d_in[3];
    const float* Wpx = (const float*)d_in[4];
    const float* bpx = (const float*)d_in[5];
    const float* Wk  = (const float*)d_in[6];
    const float* bk  = (const float*)d_in[7];
    const float* Wpy = (const float*)d_in[8];
    const float* bpy = (const float*)d_in[9];
    const float* Wv  = (const float*)d_in[10];
    const float* bv  = (const float*)d_in[11];
    float* out = (float*)d_out;

    const int proj_smem = 32 * 136 * 4 + 64 * 36 * 4;   // 26624 B
    cudaFuncSetAttribute(projqk_kernel, cudaFuncAttributeMaxDynamicSharedMemorySize,
                         proj_smem);
    cudaFuncSetAttribute(projv_qk_kernel, cudaFuncAttributeMaxDynamicSharedMemorySize,
                         QK_SMEM_BYTES);
    cudaFuncSetAttribute(pv_mma, cudaFuncAttributeMaxDynamicSharedMemorySize,
                         PV_SMEM_BYTES);

    pe_proj_kernel<<<dim3(PP, 2), CC>>>(Wpx, bpx, Wpy, bpy);        // launch 1
    projqk_kernel<<<288, 256, proj_smem>>>(zx, Wq, bq, zy, Wk, bk); // launch 2
    projv_qk_kernel<<<3072, 256, QK_SMEM_BYTES>>>(zy, Wv, bv);      // launch 3
    pv_mma<<<dim3(8, 2, 16), 256, PV_SMEM_BYTES>>>();               // launch 4 (profiled)
    reduce4<<<(BB * PP * CC / 4) / 256, 256>>>(out);                // launch 5
}

// round 15
// speedup vs baseline: 1.6869x; 1.6869x over previous
#include <cuda_runtime.h>
#include <cuda_bf16.h>
#include <cstdint>

// Fixed shapes
#define BB 4
#define CC 256
#define PP 1024
#define NK 8192
#define AA 64
#define PL (PP * NK)
#define PVSPLIT 4

// -------- device scratch --------
__device__ unsigned g_q[BB * PP * AA / 2];            // [b][p][a/2] bf16x2
__device__ unsigned g_k[BB * NK * AA / 2];            // [b][k][a/2]
__device__ unsigned g_vt[BB * CC * NK / 2];           // [b][c][k/2]  (V^T)
__device__ unsigned g_P[(size_t)BB * PL / 2];         // [b][p][k/2]
__device__ float g_peq[PP * AA];
__device__ float g_pek[PP * AA];
__device__ float g_pef[2][2][32][AA];                 // [which][part][pos][a]
__device__ float g_part[PVSPLIT * BB * PP * CC];      // fp32 partials

// -------- helpers --------
__device__ __forceinline__ uint32_t f2tf(float f) {
    uint32_t r;
    asm("cvt.rna.tf32.f32 %0, %1;" : "=r"(r) : "f"(f));
    return r;
}
__device__ __forceinline__ unsigned pack_bf16(float lo, float hi) {
    unsigned r;
    asm("cvt.rn.bf16x2.f32 %0, %1, %2;" : "=r"(r) : "f"(hi), "f"(lo));
    return r;
}
__device__ __forceinline__ void mma8(float* c, const uint32_t* a, const uint32_t* b) {
    asm volatile("mma.sync.aligned.m16n8k8.row.col.f32.tf32.tf32.f32 "
                 "{%0,%1,%2,%3}, {%4,%5,%6,%7}, {%8,%9}, {%0,%1,%2,%3};"
                 : "+f"(c[0]), "+f"(c[1]), "+f"(c[2]), "+f"(c[3])
                 : "r"(a[0]), "r"(a[1]), "r"(a[2]), "r"(a[3]), "r"(b[0]), "r"(b[1]));
}
__device__ __forceinline__ void mma16(float* c, const unsigned* a, const unsigned* b) {
    asm volatile("mma.sync.aligned.m16n8k16.row.col.f32.bf16.bf16.f32 "
                 "{%0,%1,%2,%3}, {%4,%5,%6,%7}, {%8,%9}, {%0,%1,%2,%3};"
                 : "+f"(c[0]), "+f"(c[1]), "+f"(c[2]), "+f"(c[3])
                 : "r"(a[0]), "r"(a[1]), "r"(a[2]), "r"(a[3]), "r"(b[0]), "r"(b[1]));
}
__device__ __forceinline__ void ldm_x4(unsigned* r, uint32_t addr) {
    asm volatile("ldmatrix.sync.aligned.m8n8.x4.shared.b16 {%0,%1,%2,%3}, [%4];"
                 : "=r"(r[0]), "=r"(r[1]), "=r"(r[2]), "=r"(r[3]) : "r"(addr));
}
__device__ __forceinline__ uint4 cvt4(float4 v) {
    uint4 r;
    r.x = f2tf(v.x); r.y = f2tf(v.y); r.z = f2tf(v.z); r.w = f2tf(v.w);
    return r;
}
__device__ __forceinline__ void cp_async16(uint32_t dst, const void* src) {
    asm volatile("cp.async.cg.shared.global [%0], [%1], 16;" :: "r"(dst), "l"(src));
}
#define CP_COMMIT() asm volatile("cp.async.commit_group;")
template<int N> __device__ __forceinline__ void cp_wait() {
    asm volatile("cp.async.wait_group %0;" :: "n"(N));
}
__device__ __forceinline__ uint32_t smem_u32(const void* p) {
    return (uint32_t)__cvta_generic_to_shared(p);
}

// Lane-offset builders for ldmatrix (row stride 36 uints).
__device__ __forceinline__ int laneA_off(int L) {
    return ((((L >> 3) & 1) * 8 + (L & 7)) * 36 + (L >> 4) * 4) * 4;
}
__device__ __forceinline__ int laneB_off(int L) {
    return (((L >> 4) * 8 + (L & 7)) * 36 + ((L >> 3) & 1) * 4) * 4;
}

// ============================================================================
// Kernel 1a: pe_parts — rank-decomposed PE projection.
// pe_q[p][a] = f[y][a] + g[x][a], f/g are 32x64 dots over the two 128-halves.
// Grid 4 blocks: (which, part). Bias folded into part 0.
// ============================================================================
__global__ void pe_parts(const float* __restrict__ Wpx, const float* __restrict__ bpx,
                         const float* __restrict__ Wpy, const float* __restrict__ bpy) {
    int which = blockIdx.x >> 1, part = blockIdx.x & 1;
    const float* W = which ? Wpy : Wpx;
    const float* bb = which ? bpy : bpx;

    __shared__ float pe_t[128][32];   // [i][pos]
    int tid = threadIdx.x;
    #pragma unroll
    for (int s = 0; s < 16; s++) {
        int idx = s * 256 + tid;
        int i = idx >> 5, pos = idx & 31;
        int j = i >> 1;
        float ang = (float)pos * expf(-logf(10000.0f) * (float)j / 64.0f);
        pe_t[i][pos] = (i & 1) ? cosf(ang) : sinf(ang);
    }
    __syncthreads();

    int a = tid & 63, pg = tid >> 6;   // pg in 0..3, covers pos pg*8..pg*8+7
    float acc[8];
    float binit = (part == 0) ? bb[a] : 0.0f;
    #pragma unroll
    for (int r = 0; r < 8; r++) acc[r] = binit;

    #pragma unroll 4
    for (int i = 0; i < 128; i++) {
        float w = W[a * CC + part * 128 + i];
        const float4* row = (const float4*)&pe_t[i][0];
        float4 p0 = row[pg * 2], p1 = row[pg * 2 + 1];
        acc[0] += p0.x * w; acc[1] += p0.y * w; acc[2] += p0.z * w; acc[3] += p0.w * w;
        acc[4] += p1.x * w; acc[5] += p1.y * w; acc[6] += p1.z * w; acc[7] += p1.w * w;
    }
    #pragma unroll
    for (int r = 0; r < 8; r++)
        g_pef[which][part][pg * 8 + r][a] = acc[r];
}

// ============================================================================
// Kernel 1b: pe_combine — pe[p][a] = f[y][a] + g[x][a]
// ============================================================================
__global__ void pe_combine() {
    int idx = blockIdx.x * 256 + threadIdx.x;   // 131072 total
    int which = idx >> 16;
    int rest = idx & 65535;
    int p = rest >> 6, a = rest & 63;
    int y = p >> 5, x = p & 31;
    float v = g_pef[which][0][y][a] + g_pef[which][1][x][a];
    (which ? g_pek : g_peq)[rest] = v;
}

// ============================================================================
// proj body: tf32 GEMM -> bf16 outputs, register-pipelined (streaming A loads)
// ============================================================================
__device__ __forceinline__ void proj_body(uint32_t* sm_, int m0, int n0, int z,
                                          const float* __restrict__ A,
                                          const float* __restrict__ W,
                                          const float* __restrict__ bias,
                                          int N, int mode) {
    uint32_t (*As)[136] = (uint32_t(*)[136])sm_;
    uint32_t (*Ws)[36]  = (uint32_t(*)[36])(sm_ + 32 * 136);

    A += (size_t)z * CC * PP;

    int tid = threadIdx.x;
    int wid = tid >> 5;
    int g = (tid >> 2) & 7, tg = tid & 3;
    int mbase = (wid >> 1) * 32;
    int nbase = (wid & 1) * 32;

    float acc[2][4][4];
    #pragma unroll
    for (int i = 0; i < 2; i++)
        #pragma unroll
        for (int j = 0; j < 4; j++)
            #pragma unroll
            for (int r = 0; r < 4; r++) acc[i][j][r] = 0.0f;

    float4 ar[4], wr[2];
    auto ldA = [&](int c0) {
        #pragma unroll
        for (int i = 0; i < 4; i++) {
            int idx = i * 256 + tid;
            int row = idx >> 5, c4 = idx & 31;
            ar[i] = __ldcs((const float4*)&A[(size_t)(c0 + row) * PP + m0 + c4 * 4]);
        }
    };
    auto ldW = [&](int c0) {
        #pragma unroll
        for (int i = 0; i < 2; i++) {
            int idx = i * 256 + tid;
            int row = idx >> 3, c4 = idx & 7;
            wr[i] = *(const float4*)&W[(size_t)(n0 + row) * CC + c0 + c4 * 4];
        }
    };

    ldA(0); ldW(0);

    for (int c0 = 0; c0 < CC; c0 += 32) {
        #pragma unroll
        for (int i = 0; i < 4; i++) {
            int idx = i * 256 + tid;
            int row = idx >> 5, c4 = idx & 31;
            *(uint4*)&As[row][c4 * 4] = cvt4(ar[i]);
        }
        #pragma unroll
        for (int i = 0; i < 2; i++) {
            int idx = i * 256 + tid;
            int row = idx >> 3, c4 = idx & 7;
            *(uint4*)&Ws[row][c4 * 4] = cvt4(wr[i]);
        }
        __syncthreads();

        if (c0 + 32 < CC) { ldA(c0 + 32); ldW(c0 + 32); }

        #pragma unroll
        for (int ks = 0; ks < 4; ks++) {
            int k0 = ks * 8;
            uint32_t af[2][4], bf[4][2];
            #pragma unroll
            for (int mt = 0; mt < 2; mt++) {
                int mr = mbase + mt * 16;
                af[mt][0] = As[k0 + tg][mr + g];
                af[mt][1] = As[k0 + tg][mr + g + 8];
                af[mt][2] = As[k0 + tg + 4][mr + g];
                af[mt][3] = As[k0 + tg + 4][mr + g + 8];
            }
            #pragma unroll
            for (int nt = 0; nt < 4; nt++) {
                int nr = nbase + nt * 8;
                bf[nt][0] = Ws[nr + g][k0 + tg];
                bf[nt][1] = Ws[nr + g][k0 + tg + 4];
            }
            #pragma unroll
            for (int mt = 0; mt < 2; mt++)
                #pragma unroll
                for (int nt = 0; nt < 4; nt++)
                    mma8(acc[mt][nt], af[mt], bf[nt]);
        }
        __syncthreads();
    }

    if (mode < 2) {
        const float* extra = (mode == 0) ? g_peq : g_pek;
        unsigned* C = (mode == 0 ? g_q : g_k) + (size_t)z * PP * (N / 2);
        #pragma unroll
        for (int mt = 0; mt < 2; mt++) {
            int r0 = m0 + mbase + mt * 16 + g;
            #pragma unroll
            for (int nt = 0; nt < 4; nt++) {
                int col = n0 + nbase + nt * 8 + 2 * tg;
                float b0 = bias[col], b1 = bias[col + 1];
                float e00 = extra[r0 * AA + col],       e01 = extra[r0 * AA + col + 1];
                float e10 = extra[(r0 + 8) * AA + col], e11 = extra[(r0 + 8) * AA + col + 1];
                C[r0 * (N / 2) + col / 2] =
                    pack_bf16(acc[mt][nt][0] + b0 + e00, acc[mt][nt][1] + b1 + e01);
                C[(r0 + 8) * (N / 2) + col / 2] =
                    pack_bf16(acc[mt][nt][2] + b0 + e10, acc[mt][nt][3] + b1 + e11);
            }
        }
    } else {
        __nv_bfloat16* Cs = (__nv_bfloat16*)sm_;   // 64 x 132 bf16 rows (66 uints)
        #pragma unroll
        for (int mt = 0; mt < 2; mt++) {
            int r0 = mbase + mt * 16 + g;
            #pragma unroll
            for (int nt = 0; nt < 4; nt++) {
                int col = nbase + nt * 8 + 2 * tg;
                float b0 = bias[n0 + col], b1 = bias[n0 + col + 1];
                Cs[(col)     * 132 + r0]     = __float2bfloat16(acc[mt][nt][0] + b0);
                Cs[(col + 1) * 132 + r0]     = __float2bfloat16(acc[mt][nt][1] + b1);
                Cs[(col)     * 132 + r0 + 8] = __float2bfloat16(acc[mt][nt][2] + b0);
                Cs[(col + 1) * 132 + r0 + 8] = __float2bfloat16(acc[mt][nt][3] + b1);
            }
        }
        __syncthreads();
        int b = z >> 3, page = z & 7;
        const unsigned* Csu = (const unsigned*)Cs;
        int tid2 = threadIdx.x;
        #pragma unroll
        for (int j = 0; j < 16; j++) {
            int f = j * 256 + tid2;
            int n = f >> 6, u = f & 63;
            g_vt[(size_t)(b * CC + n0 + n) * (NK / 2) + page * 512 + m0 / 2 + u] =
                Csu[n * 66 + u];
        }
    }
}

// ============================================================================
// qk body: QK^T (bf16, ldmatrix) + register-local batch softmax -> P (bf16),
// smem-staged coalesced STREAMING P writes (evict-first: protect L2 for Q/K).
// ============================================================================
#define QK_TILE (4 * 64 * 36)
#define QK_SMEM_BYTES (2 * QK_TILE * 4)   // 73728 B

__device__ __forceinline__ void qk_body(uint32_t* sm_, int qtile, int ktile) {
    const uint32_t sb = smem_u32(sm_);

    const int tid = threadIdx.x;
    const int wid = tid >> 5;
    const int L = tid & 31;
    const int g = (tid >> 2) & 7, tg = tid & 3;
    const int qbase = qtile * 64, kbase = ktile * 64;

    #pragma unroll
    for (int j = 0; j < 8; j++) {
        int f = j * 256 + tid;
        int row = f >> 3, a4 = f & 7;
        int b = row >> 6, r = row & 63;
        cp_async16(sb + (row * 36 + a4 * 4) * 4,
                   &g_q[((b << 10) + qbase + r) * 32 + a4 * 4]);
        cp_async16(sb + (QK_TILE + row * 36 + a4 * 4) * 4,
                   &g_k[((b << 13) + kbase + r) * 32 + a4 * 4]);
    }
    CP_COMMIT();
    cp_wait<0>();
    __syncthreads();

    const int wm = wid >> 2, wn = wid & 3;
    const int qrow0 = wm * 32, kcol0 = wn * 16;

    const int aoff = laneA_off(L);
    const int boff = laneB_off(L);
    const uint32_t qa_base = sb + qrow0 * 36 * 4 + aoff;
    const uint32_t kb_base = sb + QK_TILE * 4 + kcol0 * 36 * 4 + boff;

    float acc[4][2][2][4];
    #pragma unroll
    for (int b = 0; b < 4; b++)
        #pragma unroll
        for (int i = 0; i < 2; i++)
            #pragma unroll
            for (int j = 0; j < 2; j++)
                #pragma unroll
                for (int r = 0; r < 4; r++) acc[b][i][j][r] = 0.0f;

    #pragma unroll
    for (int ks = 0; ks < 4; ks++) {
        int k0b = ks * 32;
        #pragma unroll
        for (int b = 0; b < 4; b++) {
            unsigned af[2][4], bf[4];
            ldm_x4(af[0], qa_base + b * 9216 + k0b);
            ldm_x4(af[1], qa_base + b * 9216 + 16 * 36 * 4 + k0b);
            ldm_x4(bf,    kb_base + b * 9216 + k0b);
            #pragma unroll
            for (int mt = 0; mt < 2; mt++)
                #pragma unroll
                for (int nt = 0; nt < 2; nt++)
                    mma16(acc[b][mt][nt], af[mt], bf + nt * 2);
        }
    }

    __syncthreads();
    uint32_t* Ps = sm_;

    #pragma unroll
    for (int mt = 0; mt < 2; mt++) {
        int lo = qrow0 + mt * 16 + g;
        #pragma unroll
        for (int nt = 0; nt < 2; nt++) {
            int cu = kcol0 / 2 + nt * 4 + tg;
            float p[4][4];
            #pragma unroll
            for (int r = 0; r < 4; r++) {
                float s0 = acc[0][mt][nt][r] * 0.125f;
                float s1 = acc[1][mt][nt][r] * 0.125f;
                float s2 = acc[2][mt][nt][r] * 0.125f;
                float s3 = acc[3][mt][nt][r] * 0.125f;
                float m = fmaxf(fmaxf(s0, s1), fmaxf(s2, s3));
                float e0 = __expf(s0 - m), e1 = __expf(s1 - m);
                float e2 = __expf(s2 - m), e3 = __expf(s3 - m);
                float rv = 1.0f / (e0 + e1 + e2 + e3);
                p[r][0] = e0 * rv; p[r][1] = e1 * rv;
                p[r][2] = e2 * rv; p[r][3] = e3 * rv;
            }
            #pragma unroll
            for (int b = 0; b < 4; b++) {
                Ps[b * 2304 + lo * 36 + cu]       = pack_bf16(p[0][b], p[1][b]);
                Ps[b * 2304 + (lo + 8) * 36 + cu] = pack_bf16(p[2][b], p[3][b]);
            }
        }
    }
    __syncthreads();

    #pragma unroll
    for (int j = 0; j < 8; j++) {
        int f = j * 256 + tid;
        int b = f >> 9, r = (f >> 3) & 63, q4 = f & 7;
        uint4 val = *(const uint4*)&Ps[b * 2304 + r * 36 + q4 * 4];
        __stcs((uint4*)&g_P[(size_t)b * (PL / 2) + (size_t)(qbase + r) * (NK / 2)
                            + kbase / 2 + q4 * 4], val);
    }
}

// ============================================================================
// Kernel 2: merged proj_q + proj_k (288 blocks)
// ============================================================================
__global__ __launch_bounds__(256, 2) void projqk_kernel(
    const float* __restrict__ zx, const float* __restrict__ Wq, const float* __restrict__ bq,
    const float* __restrict__ zy, const float* __restrict__ Wk, const float* __restrict__ bk) {
    extern __shared__ uint32_t sm[];
    int id = blockIdx.x;
    if (id < 32) {
        proj_body(sm, (id & 7) * 128, 0, id >> 3, zx, Wq, bq, 64, 0);
    } else {
        int id2 = id - 32;
        proj_body(sm, (id2 & 7) * 128, 0, id2 >> 3, zy, Wk, bk, 64, 1);
    }
}

// ============================================================================
// Kernel 3: merged proj_v (1024) + qk (2048) = 3072 blocks, 1:2 interleave
// ============================================================================
__global__ __launch_bounds__(256, 2) void projv_qk_kernel(
    const float* __restrict__ zy, const float* __restrict__ Wv, const float* __restrict__ bv) {
    extern __shared__ uint32_t sm[];
    int idx = blockIdx.x;
    if (idx % 3 == 0) {
        int vid = idx / 3;
        proj_body(sm, (vid & 7) * 128, ((vid >> 3) & 3) * 64, vid >> 5, zy, Wv, bv, 256, 2);
    } else {
        int qkid = idx - idx / 3 - 1;
        qk_body(sm, qkid & 15, qkid >> 4);
    }
}

// ============================================================================
// Kernel 4: O = P @ V (bf16, ldmatrix), split-K=4, BK=64, 3-stage pipeline.
// ============================================================================
#define PS_BUF (128 * 36)
#define VS_BUF (128 * 36)
#define STAGE  (PS_BUF + VS_BUF)
#define PV_SMEM_BYTES (3 * STAGE * 4)   // 110592 B

__global__ __launch_bounds__(256, 2) void pv_mma() {
    extern __shared__ uint32_t sm[];
    const uint32_t sb = smem_u32(sm);

    int b = blockIdx.z >> 2;
    int split = blockIdx.z & 3;
    int m0 = blockIdx.x * 128, n0 = blockIdx.y * 128;
    int tid = threadIdx.x;
    int wid = tid >> 5;
    const int L = tid & 31;
    int g = (tid >> 2) & 7, tg = tid & 3;
    int mbase = (wid >> 1) * 32;
    int nbase = (wid & 1) * 64;

    const unsigned* Pu = g_P  + (size_t)b * (PL / 2);
    const unsigned* Vu = g_vt + (size_t)b * CC * (NK / 2);

    const int kstart = split * (NK / PVSPLIT);
    const int NIT = (NK / PVSPLIT) / 64;   // 32

    auto prefetch = [&](int it, int stage) {
        int kbu = (kstart + it * 64) / 2;
        #pragma unroll
        for (int j = 0; j < 4; j++) {
            int f = j * 256 + tid;
            int row = f >> 3, c4 = f & 7;
            uint32_t dst = sb + (stage * STAGE + row * 36 + c4 * 4) * 4;
            cp_async16(dst, Pu + (size_t)(m0 + row) * (NK / 2) + kbu + c4 * 4);
            uint32_t dst2 = sb + (stage * STAGE + PS_BUF + row * 36 + c4 * 4) * 4;
            cp_async16(dst2, Vu + (size_t)(n0 + row) * (NK / 2) + kbu + c4 * 4);
        }
        CP_COMMIT();
    };

    float acc[2][8][4];
    #pragma unroll
    for (int i = 0; i < 2; i++)
        #pragma unroll
        for (int j = 0; j < 8; j++)
            #pragma unroll
            for (int r = 0; r < 4; r++) acc[i][j][r] = 0.0f;

    const int aoff = laneA_off(L);
    const int boff = laneB_off(L);
    const uint32_t pa_base = sb + mbase * 36 * 4 + aoff;
    const uint32_t vb_base = sb + PS_BUF * 4 + nbase * 36 * 4 + boff;

    prefetch(0, 0);
    prefetch(1, 1);

    int stage = 0;
    for (int it = 0; it < NIT; it++) {
        if (it + 1 < NIT) cp_wait<1>(); else cp_wait<0>();
        __syncthreads();
        if (it + 2 < NIT) {
            int ns = stage + 2; if (ns >= 3) ns -= 3;
            prefetch(it + 2, ns);
        }

        uint32_t stg = (uint32_t)(stage * STAGE * 4);
        #pragma unroll
        for (int ks = 0; ks < 4; ks++) {
            int k0b = ks * 32;
            unsigned af[2][4], bf[4][4];
            ldm_x4(af[0], pa_base + stg + k0b);
            ldm_x4(af[1], pa_base + stg + 16 * 36 * 4 + k0b);
            #pragma unroll
            for (int j = 0; j < 4; j++)
                ldm_x4(bf[j], vb_base + stg + j * 16 * 36 * 4 + k0b);
            #pragma unroll
            for (int mt = 0; mt < 2; mt++)
                #pragma unroll
                for (int nt = 0; nt < 8; nt++)
                    mma16(acc[mt][nt], af[mt], bf[nt >> 1] + (nt & 1) * 2);
        }
        if (++stage == 3) stage = 0;
    }

    float* part = g_part + (size_t)split * (BB * PP * CC);
    #pragma unroll
    for (int mt = 0; mt < 2; mt++) {
        int r0 = m0 + mbase + mt * 16 + g;
        #pragma unroll
        for (int nt = 0; nt < 8; nt++) {
            int col = n0 + nbase + nt * 8 + 2 * tg;
            __stcs((float2*)&part[(size_t)((b << 10) + r0) * CC + col],
                   make_float2(acc[mt][nt][0], acc[mt][nt][1]));
            __stcs((float2*)&part[(size_t)((b << 10) + r0 + 8) * CC + col],
                   make_float2(acc[mt][nt][2], acc[mt][nt][3]));
        }
    }
}

// ============================================================================
// Kernel 5: deterministic 4-way split-K reduction into d_out ([b][p][c])
// ============================================================================
__global__ void reduce4(float* __restrict__ out) {
    int i = blockIdx.x * blockDim.x + threadIdx.x;
    const float4* p = (const float4*)g_part;
    const int plane = BB * PP * CC / 4;
    float4 s = __ldcs(p + i);
    #pragma unroll
    for (int sp = 1; sp < PVSPLIT; sp++) {
        float4 t = __ldcs(p + (size_t)sp * plane + i);
        s.x += t.x; s.y += t.y; s.z += t.z; s.w += t.w;
    }
    ((float4*)out)[i] = s;
}

// ============================================================================
extern "C" void kernel_launch(void* const* d_in, const int* in_sizes, int n_in,
                              void* d_out, int out_size) {
    const float* zx  = (const float*)d_in[0];
    const float* zy  = (const float*)d_in[1];
    const float* Wq  = (const float*)d_in[2];
    const float* bq  = (const float*)d_in[3];
    const float* Wpx = (const float*)d_in[4];
    const float* bpx = (const float*)d_in[5];
    const float* Wk  = (const float*)d_in[6];
    const float* bk  = (const float*)d_in[7];
    const float* Wpy = (const float*)d_in[8];
    const float* bpy = (const float*)d_in[9];
    const float* Wv  = (const float*)d_in[10];
    const float* bv  = (const float*)d_in[11];
    float* out = (float*)d_out;

    const int proj_smem = 32 * 136 * 4 + 64 * 36 * 4;   // 26624 B
    cudaFuncSetAttribute(projqk_kernel, cudaFuncAttributeMaxDynamicSharedMemorySize,
                         proj_smem);
    cudaFuncSetAttribute(projv_qk_kernel, cudaFuncAttributeMaxDynamicSharedMemorySize,
                         QK_SMEM_BYTES);
    cudaFuncSetAttribute(pv_mma, cudaFuncAttributeMaxDynamicSharedMemorySize,
                         PV_SMEM_BYTES);

    pe_parts<<<4, 256>>>(Wpx, bpx, Wpy, bpy);                       // launch 1
    pe_combine<<<512, 256>>>();                                     // launch 2
    projqk_kernel<<<288, 256, proj_smem>>>(zx, Wq, bq, zy, Wk, bk); // launch 3
    projv_qk_kernel<<<3072, 256, QK_SMEM_BYTES>>>(zy, Wv, bv);      // launch 4
    pv_mma<<<dim3(8, 2, 16), 256, PV_SMEM_BYTES>>>();               // launch 5
    reduce4<<<(BB * PP * CC / 4) / 256, 256>>>(out);                // launch 6
}

// round 16
// speedup vs baseline: 1.7358x; 1.0290x over previous
#include <cuda_runtime.h>
#include <cuda_bf16.h>
#include <cstdint>

// Fixed shapes
#define BB 4
#define CC 256
#define PP 1024
#define NK 8192
#define AA 64
#define PL (PP * NK)
#define PVSPLIT 4

// -------- device scratch --------
__device__ unsigned g_q[BB * PP * AA / 2];            // [b][p][a/2] bf16x2 (pre-scaled by 0.125)
__device__ unsigned g_k[BB * NK * AA / 2];            // [b][k][a/2]
__device__ unsigned g_vt[BB * CC * NK / 2];           // [b][c][k/2]  (V^T)
__device__ unsigned g_P[(size_t)BB * PL / 2];         // [b][p][k/2]
__device__ float g_pef[2][2][32][AA];                 // [which][part][pos][a]
__device__ float g_part[PVSPLIT * BB * PP * CC];      // fp32 partials
__device__ unsigned g_done;                           // projqk completion counter

// -------- helpers --------
__device__ __forceinline__ uint32_t f2tf(float f) {
    uint32_t r;
    asm("cvt.rna.tf32.f32 %0, %1;" : "=r"(r) : "f"(f));
    return r;
}
__device__ __forceinline__ unsigned pack_bf16(float lo, float hi) {
    unsigned r;
    asm("cvt.rn.bf16x2.f32 %0, %1, %2;" : "=r"(r) : "f"(hi), "f"(lo));
    return r;
}
__device__ __forceinline__ void mma8(float* c, const uint32_t* a, const uint32_t* b) {
    asm volatile("mma.sync.aligned.m16n8k8.row.col.f32.tf32.tf32.f32 "
                 "{%0,%1,%2,%3}, {%4,%5,%6,%7}, {%8,%9}, {%0,%1,%2,%3};"
                 : "+f"(c[0]), "+f"(c[1]), "+f"(c[2]), "+f"(c[3])
                 : "r"(a[0]), "r"(a[1]), "r"(a[2]), "r"(a[3]), "r"(b[0]), "r"(b[1]));
}
__device__ __forceinline__ void mma16(float* c, const unsigned* a, const unsigned* b) {
    asm volatile("mma.sync.aligned.m16n8k16.row.col.f32.bf16.bf16.f32 "
                 "{%0,%1,%2,%3}, {%4,%5,%6,%7}, {%8,%9}, {%0,%1,%2,%3};"
                 : "+f"(c[0]), "+f"(c[1]), "+f"(c[2]), "+f"(c[3])
                 : "r"(a[0]), "r"(a[1]), "r"(a[2]), "r"(a[3]), "r"(b[0]), "r"(b[1]));
}
__device__ __forceinline__ void ldm_x4(unsigned* r, uint32_t addr) {
    asm volatile("ldmatrix.sync.aligned.m8n8.x4.shared.b16 {%0,%1,%2,%3}, [%4];"
                 : "=r"(r[0]), "=r"(r[1]), "=r"(r[2]), "=r"(r[3]) : "r"(addr));
}
__device__ __forceinline__ uint4 cvt4(float4 v) {
    uint4 r;
    r.x = f2tf(v.x); r.y = f2tf(v.y); r.z = f2tf(v.z); r.w = f2tf(v.w);
    return r;
}
__device__ __forceinline__ void cp_async16(uint32_t dst, const void* src) {
    asm volatile("cp.async.cg.shared.global [%0], [%1], 16;" :: "r"(dst), "l"(src));
}
#define CP_COMMIT() asm volatile("cp.async.commit_group;")
template<int N> __device__ __forceinline__ void cp_wait() {
    asm volatile("cp.async.wait_group %0;" :: "n"(N));
}
__device__ __forceinline__ uint32_t smem_u32(const void* p) {
    return (uint32_t)__cvta_generic_to_shared(p);
}

// Lane-offset builders for ldmatrix (row stride 36 uints).
__device__ __forceinline__ int laneA_off(int L) {
    return ((((L >> 3) & 1) * 8 + (L & 7)) * 36 + (L >> 4) * 4) * 4;
}
__device__ __forceinline__ int laneB_off(int L) {
    return (((L >> 4) * 8 + (L & 7)) * 36 + ((L >> 3) & 1) * 4) * 4;
}

// ============================================================================
// Kernel 1: pe_parts — rank-decomposed PE projection (also resets g_done).
// ============================================================================
__global__ void pe_parts(const float* __restrict__ Wpx, const float* __restrict__ bpx,
                         const float* __restrict__ Wpy, const float* __restrict__ bpy) {
    if (threadIdx.x == 0) g_done = 0;   // all 4 blocks write 0 (benign race)

    int which = blockIdx.x >> 1, part = blockIdx.x & 1;
    const float* W = which ? Wpy : Wpx;
    const float* bb = which ? bpy : bpx;

    __shared__ float pe_t[128][32];   // [i][pos]
    int tid = threadIdx.x;
    #pragma unroll
    for (int s = 0; s < 16; s++) {
        int idx = s * 256 + tid;
        int i = idx >> 5, pos = idx & 31;
        int j = i >> 1;
        float ang = (float)pos * expf(-logf(10000.0f) * (float)j / 64.0f);
        pe_t[i][pos] = (i & 1) ? cosf(ang) : sinf(ang);
    }
    __syncthreads();

    int a = tid & 63, pg = tid >> 6;
    float acc[8];
    float binit = (part == 0) ? bb[a] : 0.0f;
    #pragma unroll
    for (int r = 0; r < 8; r++) acc[r] = binit;

    #pragma unroll 4
    for (int i = 0; i < 128; i++) {
        float w = W[a * CC + part * 128 + i];
        const float4* row = (const float4*)&pe_t[i][0];
        float4 p0 = row[pg * 2], p1 = row[pg * 2 + 1];
        acc[0] += p0.x * w; acc[1] += p0.y * w; acc[2] += p0.z * w; acc[3] += p0.w * w;
        acc[4] += p1.x * w; acc[5] += p1.y * w; acc[6] += p1.z * w; acc[7] += p1.w * w;
    }
    #pragma unroll
    for (int r = 0; r < 8; r++)
        g_pef[which][part][pg * 8 + r][a] = acc[r];
}

// ============================================================================
// proj body: tf32 GEMM -> bf16 outputs (pe inline from g_pef; q pre-scaled).
// ============================================================================
__device__ __forceinline__ void proj_body(uint32_t* sm_, int m0, int n0, int z,
                                          const float* __restrict__ A,
                                          const float* __restrict__ W,
                                          const float* __restrict__ bias,
                                          int N, int mode) {
    uint32_t (*As)[136] = (uint32_t(*)[136])sm_;
    uint32_t (*Ws)[36]  = (uint32_t(*)[36])(sm_ + 32 * 136);

    A += (size_t)z * CC * PP;

    int tid = threadIdx.x;
    int wid = tid >> 5;
    int g = (tid >> 2) & 7, tg = tid & 3;
    int mbase = (wid >> 1) * 32;
    int nbase = (wid & 1) * 32;

    float acc[2][4][4];
    #pragma unroll
    for (int i = 0; i < 2; i++)
        #pragma unroll
        for (int j = 0; j < 4; j++)
            #pragma unroll
            for (int r = 0; r < 4; r++) acc[i][j][r] = 0.0f;

    float4 ar[4], wr[2];
    auto ldA = [&](int c0) {
        #pragma unroll
        for (int i = 0; i < 4; i++) {
            int idx = i * 256 + tid;
            int row = idx >> 5, c4 = idx & 31;
            ar[i] = __ldcs((const float4*)&A[(size_t)(c0 + row) * PP + m0 + c4 * 4]);
        }
    };
    auto ldW = [&](int c0) {
        #pragma unroll
        for (int i = 0; i < 2; i++) {
            int idx = i * 256 + tid;
            int row = idx >> 3, c4 = idx & 7;
            wr[i] = *(const float4*)&W[(size_t)(n0 + row) * CC + c0 + c4 * 4];
        }
    };

    ldA(0); ldW(0);

    for (int c0 = 0; c0 < CC; c0 += 32) {
        #pragma unroll
        for (int i = 0; i < 4; i++) {
            int idx = i * 256 + tid;
            int row = idx >> 5, c4 = idx & 31;
            *(uint4*)&As[row][c4 * 4] = cvt4(ar[i]);
        }
        #pragma unroll
        for (int i = 0; i < 2; i++) {
            int idx = i * 256 + tid;
            int row = idx >> 3, c4 = idx & 7;
            *(uint4*)&Ws[row][c4 * 4] = cvt4(wr[i]);
        }
        __syncthreads();

        if (c0 + 32 < CC) { ldA(c0 + 32); ldW(c0 + 32); }

        #pragma unroll
        for (int ks = 0; ks < 4; ks++) {
            int k0 = ks * 8;
            uint32_t af[2][4], bf[4][2];
            #pragma unroll
            for (int mt = 0; mt < 2; mt++) {
                int mr = mbase + mt * 16;
                af[mt][0] = As[k0 + tg][mr + g];
                af[mt][1] = As[k0 + tg][mr + g + 8];
                af[mt][2] = As[k0 + tg + 4][mr + g];
                af[mt][3] = As[k0 + tg + 4][mr + g + 8];
            }
            #pragma unroll
            for (int nt = 0; nt < 4; nt++) {
                int nr = nbase + nt * 8;
                bf[nt][0] = Ws[nr + g][k0 + tg];
                bf[nt][1] = Ws[nr + g][k0 + tg + 4];
            }
            #pragma unroll
            for (int mt = 0; mt < 2; mt++)
                #pragma unroll
                for (int nt = 0; nt < 4; nt++)
                    mma8(acc[mt][nt], af[mt], bf[nt]);
        }
        __syncthreads();
    }

    if (mode < 2) {
        int which = mode;                 // 0 -> q (pef[0]), 1 -> k (pef[1])
        float qscale = (mode == 0) ? 0.125f : 1.0f;   // fold 1/sqrt(A) into q (exact 2^-3)
        unsigned* C = (mode == 0 ? g_q : g_k) + (size_t)z * PP * (N / 2);
        #pragma unroll
        for (int mt = 0; mt < 2; mt++) {
            int r0 = m0 + mbase + mt * 16 + g;
            int y0 = r0 >> 5, x0 = r0 & 31;
            int y1 = (r0 + 8) >> 5, x1 = (r0 + 8) & 31;
            #pragma unroll
            for (int nt = 0; nt < 4; nt++) {
                int col = n0 + nbase + nt * 8 + 2 * tg;
                float b0 = bias[col], b1 = bias[col + 1];
                float e00 = g_pef[which][0][y0][col]     + g_pef[which][1][x0][col];
                float e01 = g_pef[which][0][y0][col + 1] + g_pef[which][1][x0][col + 1];
                float e10 = g_pef[which][0][y1][col]     + g_pef[which][1][x1][col];
                float e11 = g_pef[which][0][y1][col + 1] + g_pef[which][1][x1][col + 1];
                C[r0 * (N / 2) + col / 2] =
                    pack_bf16(qscale * (acc[mt][nt][0] + b0 + e00),
                              qscale * (acc[mt][nt][1] + b1 + e01));
                C[(r0 + 8) * (N / 2) + col / 2] =
                    pack_bf16(qscale * (acc[mt][nt][2] + b0 + e10),
                              qscale * (acc[mt][nt][3] + b1 + e11));
            }
        }
    } else {
        __nv_bfloat16* Cs = (__nv_bfloat16*)sm_;   // 64 x 132 bf16 rows (66 uints)
        #pragma unroll
        for (int mt = 0; mt < 2; mt++) {
            int r0 = mbase + mt * 16 + g;
            #pragma unroll
            for (int nt = 0; nt < 4; nt++) {
                int col = nbase + nt * 8 + 2 * tg;
                float b0 = bias[n0 + col], b1 = bias[n0 + col + 1];
                Cs[(col)     * 132 + r0]     = __float2bfloat16(acc[mt][nt][0] + b0);
                Cs[(col + 1) * 132 + r0]     = __float2bfloat16(acc[mt][nt][1] + b1);
                Cs[(col)     * 132 + r0 + 8] = __float2bfloat16(acc[mt][nt][2] + b0);
                Cs[(col + 1) * 132 + r0 + 8] = __float2bfloat16(acc[mt][nt][3] + b1);
            }
        }
        __syncthreads();
        int b = z >> 3, page = z & 7;
        const unsigned* Csu = (const unsigned*)Cs;
        int tid2 = threadIdx.x;
        #pragma unroll
        for (int j = 0; j < 16; j++) {
            int f = j * 256 + tid2;
            int n = f >> 6, u = f & 63;
            g_vt[(size_t)(b * CC + n0 + n) * (NK / 2) + page * 512 + m0 / 2 + u] =
                Csu[n * 66 + u];
        }
    }
}

// ============================================================================
// qk body: QK^T (bf16, ldmatrix) + register-local batch softmax (no max-sub,
// scale folded into q) -> P (bf16), smem-staged streaming stores.
// ============================================================================
#define QK_TILE (4 * 64 * 36)
#define QK_SMEM_BYTES (2 * QK_TILE * 4)   // 73728 B

__device__ __forceinline__ void qk_body(uint32_t* sm_, int qtile, int ktile) {
    const uint32_t sb = smem_u32(sm_);

    const int tid = threadIdx.x;
    const int wid = tid >> 5;
    const int L = tid & 31;
    const int g = (tid >> 2) & 7, tg = tid & 3;
    const int qbase = qtile * 64, kbase = ktile * 64;

    #pragma unroll
    for (int j = 0; j < 8; j++) {
        int f = j * 256 + tid;
        int row = f >> 3, a4 = f & 7;
        int b = row >> 6, r = row & 63;
        cp_async16(sb + (row * 36 + a4 * 4) * 4,
                   &g_q[((b << 10) + qbase + r) * 32 + a4 * 4]);
        cp_async16(sb + (QK_TILE + row * 36 + a4 * 4) * 4,
                   &g_k[((b << 13) + kbase + r) * 32 + a4 * 4]);
    }
    CP_COMMIT();
    cp_wait<0>();
    __syncthreads();

    const int wm = wid >> 2, wn = wid & 3;
    const int qrow0 = wm * 32, kcol0 = wn * 16;

    const int aoff = laneA_off(L);
    const int boff = laneB_off(L);
    const uint32_t qa_base = sb + qrow0 * 36 * 4 + aoff;
    const uint32_t kb_base = sb + QK_TILE * 4 + kcol0 * 36 * 4 + boff;

    float acc[4][2][2][4];
    #pragma unroll
    for (int b = 0; b < 4; b++)
        #pragma unroll
        for (int i = 0; i < 2; i++)
            #pragma unroll
            for (int j = 0; j < 2; j++)
                #pragma unroll
                for (int r = 0; r < 4; r++) acc[b][i][j][r] = 0.0f;

    #pragma unroll
    for (int ks = 0; ks < 4; ks++) {
        int k0b = ks * 32;
        #pragma unroll
        for (int b = 0; b < 4; b++) {
            unsigned af[2][4], bf[4];
            ldm_x4(af[0], qa_base + b * 9216 + k0b);
            ldm_x4(af[1], qa_base + b * 9216 + 16 * 36 * 4 + k0b);
            ldm_x4(bf,    kb_base + b * 9216 + k0b);
            #pragma unroll
            for (int mt = 0; mt < 2; mt++)
                #pragma unroll
                for (int nt = 0; nt < 2; nt++)
                    mma16(acc[b][mt][nt], af[mt], bf + nt * 2);
        }
    }

    __syncthreads();
    uint32_t* Ps = sm_;

    #pragma unroll
    for (int mt = 0; mt < 2; mt++) {
        int lo = qrow0 + mt * 16 + g;
        #pragma unroll
        for (int nt = 0; nt < 2; nt++) {
            int cu = kcol0 / 2 + nt * 4 + tg;
            float p[4][4];
            #pragma unroll
            for (int r = 0; r < 4; r++) {
                // scores already scaled; softmax over 4 bounded values (no max-sub)
                float e0 = __expf(acc[0][mt][nt][r]);
                float e1 = __expf(acc[1][mt][nt][r]);
                float e2 = __expf(acc[2][mt][nt][r]);
                float e3 = __expf(acc[3][mt][nt][r]);
                float rv = 1.0f / (e0 + e1 + e2 + e3);
                p[r][0] = e0 * rv; p[r][1] = e1 * rv;
                p[r][2] = e2 * rv; p[r][3] = e3 * rv;
            }
            #pragma unroll
            for (int b = 0; b < 4; b++) {
                Ps[b * 2304 + lo * 36 + cu]       = pack_bf16(p[0][b], p[1][b]);
                Ps[b * 2304 + (lo + 8) * 36 + cu] = pack_bf16(p[2][b], p[3][b]);
            }
        }
    }
    __syncthreads();

    #pragma unroll
    for (int j = 0; j < 8; j++) {
        int f = j * 256 + tid;
        int b = f >> 9, r = (f >> 3) & 63, q4 = f & 7;
        uint4 val = *(const uint4*)&Ps[b * 2304 + r * 36 + q4 * 4];
        __stcs((uint4*)&g_P[(size_t)b * (PL / 2) + (size_t)(qbase + r) * (NK / 2)
                            + kbase / 2 + q4 * 4], val);
    }
}

// ============================================================================
// Kernel 2 (MEGA): blocks 0-287 = proj_q/k (signal g_done); blocks 288+ =
// proj_v (no wait) + qk (acquire-spin until all 288 proj_qk blocks done).
// Wave-1 schedules lowest ids first -> no deadlock.
// ============================================================================
__global__ __launch_bounds__(256, 2) void mega_kernel(
    const float* __restrict__ zx, const float* __restrict__ Wq, const float* __restrict__ bq,
    const float* __restrict__ zy, const float* __restrict__ Wk, const float* __restrict__ bk,
    const float* __restrict__ Wv, const float* __restrict__ bv) {
    extern __shared__ uint32_t sm[];
    int id = blockIdx.x;
    if (id < 288) {
        if (id < 32) {
            proj_body(sm, (id & 7) * 128, 0, id >> 3, zx, Wq, bq, 64, 0);
        } else {
            int id2 = id - 32;
            proj_body(sm, (id2 & 7) * 128, 0, id2 >> 3, zy, Wk, bk, 64, 1);
        }
        __threadfence();
        __syncthreads();
        if (threadIdx.x == 0) atomicAdd(&g_done, 1u);
    } else {
        int idx = id - 288;
        if (idx % 3 == 0) {
            int vid = idx / 3;
            proj_body(sm, (vid & 7) * 128, ((vid >> 3) & 3) * 64, vid >> 5, zy, Wv, bv, 256, 2);
        } else {
            int qkid = idx - idx / 3 - 1;
            if (threadIdx.x == 0) {
                unsigned v;
                do {
                    asm volatile("ld.acquire.gpu.u32 %0, [%1];" : "=r"(v) : "l"(&g_done));
                    if (v >= 288u) break;
                    asm volatile("nanosleep.u32 128;");
                } while (true);
            }
            __syncthreads();
            qk_body(sm, qkid & 15, qkid >> 4);
        }
    }
}

// ============================================================================
// Kernel 3: O = P @ V (bf16, ldmatrix), split-K=4, BK=64, 3-stage pipeline.
// ============================================================================
#define PS_BUF (128 * 36)
#define VS_BUF (128 * 36)
#define STAGE  (PS_BUF + VS_BUF)
#define PV_SMEM_BYTES (3 * STAGE * 4)   // 110592 B

__global__ __launch_bounds__(256, 2) void pv_mma() {
    extern __shared__ uint32_t sm[];
    const uint32_t sb = smem_u32(sm);

    int b = blockIdx.z >> 2;
    int split = blockIdx.z & 3;
    int m0 = blockIdx.x * 128, n0 = blockIdx.y * 128;
    int tid = threadIdx.x;
    int wid = tid >> 5;
    const int L = tid & 31;
    int g = (tid >> 2) & 7, tg = tid & 3;
    int mbase = (wid >> 1) * 32;
    int nbase = (wid & 1) * 64;

    const unsigned* Pu = g_P  + (size_t)b * (PL / 2);
    const unsigned* Vu = g_vt + (size_t)b * CC * (NK / 2);

    const int kstart = split * (NK / PVSPLIT);
    const int NIT = (NK / PVSPLIT) / 64;   // 32

    auto prefetch = [&](int it, int stage) {
        int kbu = (kstart + it * 64) / 2;
        #pragma unroll
        for (int j = 0; j < 4; j++) {
            int f = j * 256 + tid;
            int row = f >> 3, c4 = f & 7;
            uint32_t dst = sb + (stage * STAGE + row * 36 + c4 * 4) * 4;
            cp_async16(dst, Pu + (size_t)(m0 + row) * (NK / 2) + kbu + c4 * 4);
            uint32_t dst2 = sb + (stage * STAGE + PS_BUF + row * 36 + c4 * 4) * 4;
            cp_async16(dst2, Vu + (size_t)(n0 + row) * (NK / 2) + kbu + c4 * 4);
        }
        CP_COMMIT();
    };

    float acc[2][8][4];
    #pragma unroll
    for (int i = 0; i < 2; i++)
        #pragma unroll
        for (int j = 0; j < 8; j++)
            #pragma unroll
            for (int r = 0; r < 4; r++) acc[i][j][r] = 0.0f;

    const int aoff = laneA_off(L);
    const int boff = laneB_off(L);
    const uint32_t pa_base = sb + mbase * 36 * 4 + aoff;
    const uint32_t vb_base = sb + PS_BUF * 4 + nbase * 36 * 4 + boff;

    prefetch(0, 0);
    prefetch(1, 1);

    int stage = 0;
    for (int it = 0; it < NIT; it++) {
        if (it + 1 < NIT) cp_wait<1>(); else cp_wait<0>();
        __syncthreads();
        if (it + 2 < NIT) {
            int ns = stage + 2; if (ns >= 3) ns -= 3;
            prefetch(it + 2, ns);
        }

        uint32_t stg = (uint32_t)(stage * STAGE * 4);
        #pragma unroll
        for (int ks = 0; ks < 4; ks++) {
            int k0b = ks * 32;
            unsigned af[2][4], bf[4][4];
            ldm_x4(af[0], pa_base + stg + k0b);
            ldm_x4(af[1], pa_base + stg + 16 * 36 * 4 + k0b);
            #pragma unroll
            for (int j = 0; j < 4; j++)
                ldm_x4(bf[j], vb_base + stg + j * 16 * 36 * 4 + k0b);
            #pragma unroll
            for (int mt = 0; mt < 2; mt++)
                #pragma unroll
                for (int nt = 0; nt < 8; nt++)
                    mma16(acc[mt][nt], af[mt], bf[nt >> 1] + (nt & 1) * 2);
        }
        if (++stage == 3) stage = 0;
    }

    float* part = g_part + (size_t)split * (BB * PP * CC);
    #pragma unroll
    for (int mt = 0; mt < 2; mt++) {
        int r0 = m0 + mbase + mt * 16 + g;
        #pragma unroll
        for (int nt = 0; nt < 8; nt++) {
            int col = n0 + nbase + nt * 8 + 2 * tg;
            __stcs((float2*)&part[(size_t)((b << 10) + r0) * CC + col],
                   make_float2(acc[mt][nt][0], acc[mt][nt][1]));
            __stcs((float2*)&part[(size_t)((b << 10) + r0 + 8) * CC + col],
                   make_float2(acc[mt][nt][2], acc[mt][nt][3]));
        }
    }
}

// ============================================================================
// Kernel 4: deterministic 4-way split-K reduction into d_out ([b][p][c])
// ============================================================================
__global__ void reduce4(float* __restrict__ out) {
    int i = blockIdx.x * blockDim.x + threadIdx.x;
    const float4* p = (const float4*)g_part;
    const int plane = BB * PP * CC / 4;
    float4 s = __ldcs(p + i);
    #pragma unroll
    for (int sp = 1; sp < PVSPLIT; sp++) {
        float4 t = __ldcs(p + (size_t)sp * plane + i);
        s.x += t.x; s.y += t.y; s.z += t.z; s.w += t.w;
    }
    ((float4*)out)[i] = s;
}

// ============================================================================
extern "C" void kernel_launch(void* const* d_in, const int* in_sizes, int n_in,
                              void* d_out, int out_size) {
    const float* zx  = (const float*)d_in[0];
    const float* zy  = (const float*)d_in[1];
    const float* Wq  = (const float*)d_in[2];
    const float* bq  = (const float*)d_in[3];
    const float* Wpx = (const float*)d_in[4];
    const float* bpx = (const float*)d_in[5];
    const float* Wk  = (const float*)d_in[6];
    const float* bk  = (const float*)d_in[7];
    const float* Wpy = (const float*)d_in[8];
    const float* bpy = (const float*)d_in[9];
    const float* Wv  = (const float*)d_in[10];
    const float* bv  = (const float*)d_in[11];
    float* out = (float*)d_out;

    cudaFuncSetAttribute(mega_kernel, cudaFuncAttributeMaxDynamicSharedMemorySize,
                         QK_SMEM_BYTES);
    cudaFuncSetAttribute(pv_mma, cudaFuncAttributeMaxDynamicSharedMemorySize,
                         PV_SMEM_BYTES);

    pe_parts<<<4, 256>>>(Wpx, bpx, Wpy, bpy);                       // launch 1
    mega_kernel<<<3360, 256, QK_SMEM_BYTES>>>(zx, Wq, bq, zy, Wk, bk, Wv, bv); // launch 2
    pv_mma<<<dim3(8, 2, 16), 256, PV_SMEM_BYTES>>>();               // launch 3
    reduce4<<<(BB * PP * CC / 4) / 256, 256>>>(out);                // launch 4
}